// round 17
// baseline (speedup 1.0000x reference)
#include <cuda_runtime.h>

// HH_Gap: B=16, N=4096, L=512. One trajectory per thread (8192 threads),
// f32x2 packing of independent ops. Frozen arithmetic (XLA:CPU aarch64
// emulation, rel_err 4.920904e-4). Round 17:
//  * bM-division packed with h-gate division (per-lane == scalar fdiv)
//  * source order tuned to the critical chain: eB exp first, out_sig in
//    the exp shadow, gate prep in the bM-div shadow

typedef unsigned long long u64;

#define NSTEPS 4096
#define LL 512
#define NTHREADS 8192

__device__ __forceinline__ float fm(float a, float b) { return __fmul_rn(a, b); }
__device__ __forceinline__ float fa(float a, float b) { return __fadd_rn(a, b); }
__device__ __forceinline__ float ff(float a, float b, float c) { return __fmaf_rn(a, b, c); }

__device__ __forceinline__ u64 pk(float lo, float hi) {
    u64 d; asm("mov.b64 %0, {%1, %2};" : "=l"(d) : "f"(lo), "f"(hi)); return d;
}
__device__ __forceinline__ void upk(float& lo, float& hi, u64 d) {
    asm("mov.b64 {%0, %1}, %2;" : "=f"(lo), "=f"(hi) : "l"(d));
}
__device__ __forceinline__ u64 mul2(u64 a, u64 b) {
    u64 d; asm("mul.rn.f32x2 %0, %1, %2;" : "=l"(d) : "l"(a), "l"(b)); return d;
}
__device__ __forceinline__ u64 add2(u64 a, u64 b) {
    u64 d; asm("add.rn.f32x2 %0, %1, %2;" : "=l"(d) : "l"(a), "l"(b)); return d;
}
__device__ __forceinline__ u64 fma2(u64 a, u64 b, u64 c) {
    u64 d; asm("fma.rn.f32x2 %0, %1, %2, %3;" : "=l"(d) : "l"(a), "l"(b), "l"(c)); return d;
}
__device__ __forceinline__ u64 neg2(u64 a) { return a ^ 0x8000000080000000ULL; }
__device__ __forceinline__ float rcpa(float x) {
    float r; asm("rcp.approx.f32 %0, %1;" : "=f"(r) : "f"(x)); return r;
}
__device__ __forceinline__ float ex2a(float x) {
    float r; asm("ex2.approx.f32 %0, %1;" : "=f"(r) : "f"(x)); return r;
}
__device__ __forceinline__ u64 cpair(float c) { return pk(c, c); }

// Packed correctly-rounded division (FCHK-free fast path; per-lane identical
// to the frozen scalar sequence).
__device__ __forceinline__ u64 div2(u64 a, u64 b) {
    float b0, b1; upk(b0, b1, b);
    u64 r = pk(rcpa(b0), rcpa(b1));
    u64 nb = neg2(b);
    u64 one = cpair(1.0f);
    u64 e = fma2(nb, r, one);
    r = fma2(r, e, r);
    u64 q = mul2(a, r);
    u64 rem = fma2(nb, q, a);
    return fma2(rem, r, q);
}
// Packed const-denominator division (hoisted refined reciprocal pair).
__device__ __forceinline__ u64 fdc2(u64 a, u64 nb, u64 rp) {
    u64 q = mul2(a, rp);
    u64 rem = fma2(nb, q, a);
    return fma2(rem, rp, q);
}
__device__ __forceinline__ float rcp_ref(float b) {
    float r = rcpa(b);
    float e = __fmaf_rn(-b, r, 1.0f);
    return __fmaf_rn(r, e, r);
}
__device__ __forceinline__ float fdiv(float a, float b) {
    float r = rcp_ref(b);
    float q = __fmul_rn(a, r);
    float rem = __fmaf_rn(-b, q, a);
    return __fmaf_rn(rem, r, q);
}

// Packed Eigen/XLA-CPU Cephes pexp, bit-identical per lane; floor via
// __fadd_rd magic (exact), RD sum doubles as the ldexp bit source.
__device__ __forceinline__ u64 eexp2(u64 x) {
    u64 t = fma2(x, cpair(1.44269504088896341f), cpair(0.5f));
    float t0, t1; upk(t0, t1, t);
    float trm0 = __fadd_rd(t0, 12582912.0f);
    float trm1 = __fadd_rd(t1, 12582912.0f);
    u64 mv = add2(pk(trm0, trm1), cpair(-12582912.0f));  // exact floor(t)
    u64 r = fma2(mv, cpair(-0.693359375f), x);
    r = fma2(mv, cpair(2.12194440e-4f), r);
    u64 r2 = mul2(r, r);
    u64 r3 = mul2(r2, r);
    u64 y  = fma2(cpair(1.9875691500e-4f), r, cpair(1.3981999507e-3f));
    u64 y1 = fma2(cpair(4.1665795894e-2f), r, cpair(1.6666665459e-1f));
    u64 y2 = add2(r, cpair(1.0f));
    y  = fma2(y, r, cpair(8.3334519073e-3f));
    y1 = fma2(y1, r, cpair(5.0000001201e-1f));
    y  = fma2(y, r3, y1);
    y  = fma2(y, r2, y2);
    int s0 = (__float_as_int(trm0) + 127 - 0x4B400000) << 23;
    int s1 = (__float_as_int(trm1) + 127 - 0x4B400000) << 23;
    return mul2(y, pk(__int_as_float(s0), __int_as_float(s1)));
}

// Output sigmoid (off the amplified path; approx ok at the 4.92e-4 floor).
__device__ __forceinline__ float out_sig(float V) {
    float a = ff(V, -0.4808983469629878f, -9.617966939259756f);
    return rcpa(fa(1.0f, ex2a(a)));
}

__global__ __launch_bounds__(64, 1)
void hh_gap_kernel(const float* __restrict__ z, float* __restrict__ out) {
    int tid = blockIdx.x * blockDim.x + threadIdx.x;   // 0..8191
    int b = tid >> 9;
    int l = tid & (LL - 1);
    const float* zp = z   + (size_t)b * NSTEPS * LL + l;
    float*       op = out + (size_t)b * NSTEPS * LL + l;

    const u64 rp9   = cpair(rcp_ref(9.0f)),  nb9  = cpair(-9.0f);
    const u64 rp12  = cpair(rcp_ref(12.0f)), nb12 = cpair(-12.0f);
    const float r197 = rcp_ref(19.7f);
    const u64 one = cpair(1.0f), mone = cpair(-1.0f);

    float V = -70.0f, h = 1.0f;
    u64 mn = pk(0.0f, 0.0f);                 // (m, n) packed state

    op[0] = out_sig(V);

    float zbuf[4];
#pragma unroll
    for (int i = 0; i < 4; ++i) zbuf[i] = __ldcg(zp + i * LL);

    for (int t = 0; t < NSTEPS / 4; ++t) {
#pragma unroll
        for (int j = 0; j < 4; ++j) {
            int kz = t * 4 + j;
            float zprev = zbuf[j];
            int pidx = kz + 4;
            if (pidx < NSTEPS - 1) zbuf[j] = __ldcg(zp + (size_t)pidx * LL);

            // ---- powers: (m,n) packed ----
            float mlo, nlo; upk(mlo, nlo, mn);
            u64 mm_nn = mul2(mn, mn);                      // (m*m, n*n)
            float mm, nn; upk(mm, nn, mm_nn);
            u64 m3_n4 = mul2(pk(mlo, nn), pk(mm, nn));     // (m3, n4)
            u64 pp    = mul2(pk(40.0f, 35.0f), m3_n4);     // (40m3, 35n4)
            u64 pow12 = mul2(pp, pk(h, 1.0f));             // (*h, *1: exact)
            float pow1, pow2; upk(pow1, pow2, pow12);

            // (S,E) packed: lane0 fma(pow1,1,pow2) == fadd(pow1,pow2)
            float p277 = fm(pow2, -77.0f);
            u64 SE = fma2(pk(pow1, pow1), pk(1.0f, 55.0f), pk(pow2, p277));
            SE = add2(SE, pk(0.3f, -19.5f));               // (S, E)
            float S, E; upk(S, E, SE);
            float G  = fm(0.025f, S);
            u64 Gpm = fma2(pk(G, G), pk(-1.0f, 1.0f), one);  // (1-G, 1+G)
            float oneMinusG, onePlusG; upk(oneMinusG, onePlusG, Gpm);
            float EZ = fa(E, zprev);
            float num = ff(V, oneMinusG, fm(0.05f, EZ));
            float Vn  = fdiv(num, onePlusG);

            // ---- exp args; critical (eB) path first ----
            u64 VnVn = pk(Vn, Vn);
            u64 v25_35 = add2(VnVn, pk(-25.0f, 35.0f));    // (Vn-25, Vn+35)
            u64 d25_9v = fdc2(v25_35, nb9, rp9);
            u64 v90_34 = add2(VnVn, pk(90.0f, 34.0f));
            u64 d90_34 = fdc2(v90_34, nb12, rp12);
            float d25, d9v; upk(d25, d9v, d25_9v);
            float d90, d34; upk(d90, d34, d90_34);

            // CRITICAL exp first: (eB, eAH)
            u64 eB_AH = eexp2(pk(d9v, -d90));
            u64 eNM   = eexp2(neg2(d25_9v));               // (eN, eM)
            float v70 = fa(Vn, -70.0f);
            float q70 = __fmul_rn(v70, r197);
            float rem70 = __fmaf_rn(-19.7f, q70, v70);
            float d70 = __fmaf_rn(rem70, r197, q70);
            u64 eBNBH = eexp2(pk(-d70, d34));              // (eBN, eBH)

            // out_sig fills the exp-chain shadow (depends only on Vn)
            float y = out_sig(Vn);
            if (kz < NSTEPS - 1) __stcs(op + (size_t)(kz + 1) * LL, y);

            // ---- rates ----
            float eB, eAH; upk(eB, eAH, eB_AH);
            float vm25, vp35; upk(vm25, vp35, v25_35);
            float dB = fa(1.0f, -eB);
            float bMnum = fm(-0.124f, vp35);
            float aH = fm(0.25f, eAH);
            float eBN, eBH; upk(eBN, eBH, eBNBH);

            // h-gate prep (independent of bM) — scheduled into bM-div shadow
            float ABh = ff(0.25f, eBH, aH);
            float sH  = fm(0.025f, ABh);
            float umH = fa(1.0f, -sH);
            float dmH = fa(sH, 1.0f);
            float hnum = ff(aH, 0.05f, fm(umH, h));

            // packed (bM, h) division — per-lane identical to scalar fdiv
            u64 bMh = div2(pk(bMnum, hnum), pk(dB, dmH));
            float bM, hnew; upk(bM, hnew, bMh);
            bM = (dB == 0.0f) ? 1.116f : bM;
            h = hnew;

            // aN/aM packed rate division
            u64 dNM = fma2(eNM, mone, one);                // (1-eN, 1-eM)
            u64 ratnum = mul2(pk(0.02f, 0.182f), v25_35);
            u64 aNM = div2(ratnum, dNM);
            float dN, dM; upk(dN, dM, dNM);
            float aN, aM; upk(aN, aM, aNM);
            aN = (dN == 0.0f) ? 0.18f  : aN;
            aM = (dM == 0.0f) ? 1.638f : aM;

            // ---- CN gates: m,n packed ----
            float ABm = fa(aM, bM);
            float ABn = ff(0.125f, eBN, aN);
            u64 AB  = pk(ABm, ABn);
            u64 s2  = mul2(cpair(0.025f), AB);
            u64 um2 = fma2(s2, mone, one);                 // == fa(1,-s) bitwise
            u64 dm2 = add2(s2, one);
            u64 gnum = fma2(pk(aM, aN), cpair(0.05f), mul2(um2, mn));
            mn = div2(gnum, dm2);

            V = Vn;
        }
    }
}

extern "C" void kernel_launch(void* const* d_in, const int* in_sizes, int n_in,
                              void* d_out, int out_size) {
    const float* z = (const float*)d_in[0];
    float* out = (float*)d_out;
    (void)in_sizes; (void)n_in; (void)out_size;
    hh_gap_kernel<<<NTHREADS / 64, 64>>>(z, out);
}